// round 2
// baseline (speedup 1.0000x reference)
#include <cuda_runtime.h>

#define NN   100000
#define FH   8
#define EMAX 3200000
#define FIN  256

// -------- device scratch (no allocations allowed) --------
__device__ int    g_src[EMAX];
__device__ int    g_dst[EMAX];
__device__ float  g_e  [EMAX];
__device__ float4 g_h4  [NN * 2];   // h: [NN, 8] as float4 pairs (16B aligned)
__device__ float4 g_num4[NN * 2];   // numerator accumulator
__device__ float4 g_x14 [NN * 2];   // layer-1 output
__device__ float  g_as [NN];
__device__ float  g_ad [NN];
__device__ float  g_m  [NN];        // segment max
__device__ float  g_s  [NN];        // segment sum of exp

__device__ __forceinline__ float leaky02(float v) {
    return v >= 0.f ? v : 0.2f * v;
}

__device__ __forceinline__ void atomicMaxFloat(float* addr, float v) {
    // signed-int max for v>=0, unsigned min for v<0; total order matches float
    if (v >= 0.f) atomicMax((int*)addr, __float_as_int(v));
    else          atomicMin((unsigned int*)addr, __float_as_uint(v));
}

// ---------------- layer 1: h = x @ W1, a_s, a_d, m=self-loop logit ----------
// one warp per node; coalesced reads of x
__global__ void k_h1(const float* __restrict__ x, const float* __restrict__ W,
                     const float* __restrict__ att_s, const float* __restrict__ att_d) {
    __shared__ float Ws[FIN * FH];  // 8 KB
    for (int i = threadIdx.x; i < FIN * FH; i += blockDim.x) Ws[i] = W[i];
    __syncthreads();

    int warp = (blockIdx.x * blockDim.x + threadIdx.x) >> 5;
    int lane = threadIdx.x & 31;
    if (warp >= NN) return;

    const float* xr = x + (size_t)warp * FIN;
    float acc[FH];
#pragma unroll
    for (int j = 0; j < FH; j++) acc[j] = 0.f;

#pragma unroll
    for (int i = 0; i < FIN / 32; i++) {
        int k = i * 32 + lane;
        float xv = xr[k];
#pragma unroll
        for (int j = 0; j < FH; j++) acc[j] = fmaf(xv, Ws[k * FH + j], acc[j]);
    }
#pragma unroll
    for (int j = 0; j < FH; j++) {
#pragma unroll
        for (int o = 16; o > 0; o >>= 1)
            acc[j] += __shfl_xor_sync(0xffffffffu, acc[j], o);
    }
    float* gh = (float*)&g_h4[warp * 2];
    if (lane < FH) gh[lane] = acc[lane];
    if (lane == 0) {
        float as = 0.f, ad = 0.f;
#pragma unroll
        for (int j = 0; j < FH; j++) { as += acc[j] * att_s[j]; ad += acc[j] * att_d[j]; }
        g_as[warp] = as;
        g_ad[warp] = ad;
        g_m[warp]  = leaky02(as + ad);  // self-loop logit seeds the max
    }
}

// ---- layer-1 edge pass A: copy int32 idx into scratch, compute e, atomic max
__global__ void k_edge1(const int* __restrict__ ei, int E) {
    int i = blockIdx.x * blockDim.x + threadIdx.x;
    if (i >= E) return;
    int s = ei[i];
    int d = ei[E + i];
    g_src[i] = s;
    g_dst[i] = d;
    float e = leaky02(g_as[s] + g_ad[d]);
    g_e[i] = e;
    atomicMaxFloat(&g_m[d], e);
}

// ---- edge pass A for layer 2 (indices already staged) ----------------------
__global__ void k_edge2(int E) {
    int i = blockIdx.x * blockDim.x + threadIdx.x;
    if (i >= E) return;
    int s = g_src[i];
    int d = g_dst[i];
    float e = leaky02(g_as[s] + g_ad[d]);
    g_e[i] = e;
    atomicMaxFloat(&g_m[d], e);
}

// ---- node init: seed s and num with the self-loop contribution -------------
__global__ void k_inits() {
    int n = blockIdx.x * blockDim.x + threadIdx.x;
    if (n >= NN) return;
    float es = leaky02(g_as[n] + g_ad[n]);
    float t = __expf(es - g_m[n]);
    g_s[n] = t;
    float4 h0 = g_h4[n * 2], h1 = g_h4[n * 2 + 1];
    h0.x *= t; h0.y *= t; h0.z *= t; h0.w *= t;
    h1.x *= t; h1.y *= t; h1.z *= t; h1.w *= t;
    g_num4[n * 2]     = h0;
    g_num4[n * 2 + 1] = h1;
}

// ---- edge pass B: exp, scatter-add s and num --------------------------------
__global__ void k_accum(int E) {
    int i = blockIdx.x * blockDim.x + threadIdx.x;
    if (i >= E) return;
    int s = g_src[i];
    int d = g_dst[i];
    float ex = __expf(g_e[i] - g_m[d]);
    atomicAdd(&g_s[d], ex);
    const float4 h0 = g_h4[s * 2];
    const float4 h1 = g_h4[s * 2 + 1];
    float* nd = (float*)&g_num4[d * 2];
    atomicAdd(nd + 0, ex * h0.x);
    atomicAdd(nd + 1, ex * h0.y);
    atomicAdd(nd + 2, ex * h0.z);
    atomicAdd(nd + 3, ex * h0.w);
    atomicAdd(nd + 4, ex * h1.x);
    atomicAdd(nd + 5, ex * h1.y);
    atomicAdd(nd + 6, ex * h1.z);
    atomicAdd(nd + 7, ex * h1.w);
}

// ---- finalize layer 1: x1 = num/s + b1 -------------------------------------
__global__ void k_fin1(const float* __restrict__ b) {
    int n = blockIdx.x * blockDim.x + threadIdx.x;
    if (n >= NN) return;
    float inv = 1.f / g_s[n];
    float4 n0 = g_num4[n * 2], n1 = g_num4[n * 2 + 1];
    float4 r0, r1;
    r0.x = n0.x * inv + b[0]; r0.y = n0.y * inv + b[1];
    r0.z = n0.z * inv + b[2]; r0.w = n0.w * inv + b[3];
    r1.x = n1.x * inv + b[4]; r1.y = n1.y * inv + b[5];
    r1.z = n1.z * inv + b[6]; r1.w = n1.w * inv + b[7];
    g_x14[n * 2]     = r0;
    g_x14[n * 2 + 1] = r1;
}

// ---- layer 2 feature transform: h2 = x1 @ W2, a_s2, a_d2, m seed -----------
__global__ void k_h2(const float* __restrict__ W2,
                     const float* __restrict__ att_s, const float* __restrict__ att_d) {
    int n = blockIdx.x * blockDim.x + threadIdx.x;
    if (n >= NN) return;
    float xi[FH];
    const float4 a = g_x14[n * 2];
    const float4 b = g_x14[n * 2 + 1];
    xi[0] = a.x; xi[1] = a.y; xi[2] = a.z; xi[3] = a.w;
    xi[4] = b.x; xi[5] = b.y; xi[6] = b.z; xi[7] = b.w;
    float acc[FH];
#pragma unroll
    for (int j = 0; j < FH; j++) acc[j] = 0.f;
#pragma unroll
    for (int k = 0; k < FH; k++) {
        float xv = xi[k];
#pragma unroll
        for (int j = 0; j < FH; j++) acc[j] = fmaf(xv, __ldg(&W2[k * FH + j]), acc[j]);
    }
    float as = 0.f, ad = 0.f;
    float* gh = (float*)&g_h4[n * 2];
#pragma unroll
    for (int j = 0; j < FH; j++) {
        gh[j] = acc[j];
        as += acc[j] * __ldg(&att_s[j]);
        ad += acc[j] * __ldg(&att_d[j]);
    }
    g_as[n] = as;
    g_ad[n] = ad;
    g_m[n]  = leaky02(as + ad);
}

// ---- finalize layer 2 + linear head + LeakyReLU(0.01) ----------------------
__global__ void k_final(const float* __restrict__ b2, const float* __restrict__ Wl,
                        const float* __restrict__ bl, float* __restrict__ out) {
    int n = blockIdx.x * blockDim.x + threadIdx.x;
    if (n >= NN) return;
    float inv = 1.f / g_s[n];
    const float* nd = (const float*)&g_num4[n * 2];
    float acc = __ldg(&bl[0]);
#pragma unroll
    for (int j = 0; j < FH; j++) {
        float v = nd[j] * inv + __ldg(&b2[j]);
        acc = fmaf(v, __ldg(&Wl[j]), acc);
    }
    out[n] = acc >= 0.f ? acc : 0.01f * acc;
}

extern "C" void kernel_launch(void* const* d_in, const int* in_sizes, int n_in,
                              void* d_out, int out_size) {
    const float* x  = (const float*)d_in[0];
    const int*   ei = (const int*)d_in[1];      // int64 narrowed to int32 by harness
    // d_in[2] edge_type, d_in[3] edge_time: unused by the reference forward
    const float* W1   = (const float*)d_in[4];
    const float* as1  = (const float*)d_in[5];
    const float* ad1  = (const float*)d_in[6];
    const float* b1   = (const float*)d_in[7];
    const float* W2   = (const float*)d_in[8];
    const float* as2  = (const float*)d_in[9];
    const float* ad2  = (const float*)d_in[10];
    const float* b2   = (const float*)d_in[11];
    const float* Wlin = (const float*)d_in[12];
    const float* blin = (const float*)d_in[13];
    float* out = (float*)d_out;

    const int E = in_sizes[1] / 2;

    const int TB = 256;
    const int gridN  = (NN + TB - 1) / TB;            // node-per-thread kernels
    const int gridNW = (NN * 32 + TB - 1) / TB;       // warp-per-node kernel
    const int gridE  = (E + TB - 1) / TB;             // edge kernels

    // ---- layer 1 ----
    k_h1   <<<gridNW, TB>>>(x, W1, as1, ad1);
    k_edge1<<<gridE,  TB>>>(ei, E);
    k_inits<<<gridN,  TB>>>();
    k_accum<<<gridE,  TB>>>(E);
    k_fin1 <<<gridN,  TB>>>(b1);

    // ---- layer 2 ----
    k_h2   <<<gridN,  TB>>>(W2, as2, ad2);
    k_edge2<<<gridE,  TB>>>(E);
    k_inits<<<gridN,  TB>>>();
    k_accum<<<gridE,  TB>>>(E);
    k_final<<<gridN,  TB>>>(b2, Wlin, blin, out);
}

// round 3
// speedup vs baseline: 1.6833x; 1.6833x over previous
#include <cuda_runtime.h>

#define NN     100000
#define FH     8
#define EMAX   3200000
#define FIN    256
#define SCANB  512
#define NBLK   ((NN + SCANB - 1) / SCANB)   // 196

// -------- device scratch --------
__device__ int    g_ssrc[EMAX];     // src sorted by dst (CSR adjacency)
__device__ float  g_e  [EMAX];      // cached logits in CSR order
__device__ int    g_deg [NN];
__device__ int    g_part[NN];       // per-block exclusive partial
__device__ int    g_bsum[NBLK];
__device__ int    g_bsumx[NBLK];    // scanned block sums
__device__ int    g_off [NN + 1];   // CSR row offsets
__device__ int    g_cur [NN];       // scatter cursors
__device__ float4 g_h4  [NN * 2];   // transformed features [NN,8]
__device__ float4 g_x14 [NN * 2];   // layer-1 output
__device__ float  g_as [NN];
__device__ float  g_ad [NN];

__device__ __forceinline__ float leaky02(float v) { return v >= 0.f ? v : 0.2f * v; }

// ---------------- layer 1 transform: h = x @ W1, a_s, a_d; zero deg ---------
__global__ void k_h1(const float* __restrict__ x, const float* __restrict__ W,
                     const float* __restrict__ att_s, const float* __restrict__ att_d) {
    __shared__ float Ws[FIN * FH];
    for (int i = threadIdx.x; i < FIN * FH; i += blockDim.x) Ws[i] = W[i];
    __syncthreads();

    int warp = (blockIdx.x * blockDim.x + threadIdx.x) >> 5;
    int lane = threadIdx.x & 31;
    if (warp >= NN) return;

    const float* xr = x + (size_t)warp * FIN;
    float acc[FH];
#pragma unroll
    for (int j = 0; j < FH; j++) acc[j] = 0.f;
#pragma unroll
    for (int i = 0; i < FIN / 32; i++) {
        int k = i * 32 + lane;
        float xv = xr[k];
#pragma unroll
        for (int j = 0; j < FH; j++) acc[j] = fmaf(xv, Ws[k * FH + j], acc[j]);
    }
#pragma unroll
    for (int j = 0; j < FH; j++) {
#pragma unroll
        for (int o = 16; o > 0; o >>= 1) acc[j] += __shfl_xor_sync(0xffffffffu, acc[j], o);
    }
    float* gh = (float*)&g_h4[warp * 2];
    if (lane < FH) gh[lane] = acc[lane];
    if (lane == 0) {
        float as = 0.f, ad = 0.f;
#pragma unroll
        for (int j = 0; j < FH; j++) { as += acc[j] * att_s[j]; ad += acc[j] * att_d[j]; }
        g_as[warp] = as;
        g_ad[warp] = ad;
        g_deg[warp] = 0;
    }
}

// ---------------- CSR build ----------------
__global__ void k_count(const int* __restrict__ ei, int E) {
    int i = blockIdx.x * blockDim.x + threadIdx.x;
    if (i >= E) return;
    atomicAdd(&g_deg[ei[E + i]], 1);
}

__global__ void k_scan1() {
    __shared__ int sm[SCANB];
    int idx = blockIdx.x * SCANB + threadIdx.x;
    int v = (idx < NN) ? g_deg[idx] : 0;
    sm[threadIdx.x] = v;
    __syncthreads();
#pragma unroll
    for (int o = 1; o < SCANB; o <<= 1) {
        int t = (threadIdx.x >= o) ? sm[threadIdx.x - o] : 0;
        __syncthreads();
        sm[threadIdx.x] += t;
        __syncthreads();
    }
    if (idx < NN) g_part[idx] = sm[threadIdx.x] - v;   // exclusive
    if (threadIdx.x == SCANB - 1) g_bsum[blockIdx.x] = sm[SCANB - 1];
}

__global__ void k_scan2() {
    if (threadIdx.x == 0) {
        int run = 0;
        for (int b = 0; b < NBLK; b++) { g_bsumx[b] = run; run += g_bsum[b]; }
    }
}

__global__ void k_scan3(int E) {
    int idx = blockIdx.x * blockDim.x + threadIdx.x;
    if (idx >= NN) return;
    int o = g_part[idx] + g_bsumx[idx >> 9];
    g_off[idx] = o;
    g_cur[idx] = o;
    if (idx == 0) g_off[NN] = E;
}

__global__ void k_scatter(const int* __restrict__ ei, int E) {
    int i = blockIdx.x * blockDim.x + threadIdx.x;
    if (i >= E) return;
    int s = ei[i];
    int d = ei[E + i];
    int pos = atomicAdd(&g_cur[d], 1);
    g_ssrc[pos] = s;
}

// ---------------- fused gather: softmax + aggregate, warp per node ----------
// PHASE 0: epilogue writes x1 = num/den + b. PHASE 1: epilogue = head.
template <int PHASE>
__global__ void k_gather(const float* __restrict__ bv,
                         const float* __restrict__ Wl, const float* __restrict__ bl,
                         float* __restrict__ out) {
    int warp = (blockIdx.x * blockDim.x + threadIdx.x) >> 5;
    int lane = threadIdx.x & 31;
    if (warp >= NN) return;

    int beg = g_off[warp], end = g_off[warp + 1];
    float ad = g_ad[warp];
    float self_e = leaky02(g_as[warp] + ad);
    float m = self_e;

    for (int i = beg + lane; i < end; i += 32) {
        int s = g_ssrc[i];
        float e = leaky02(g_as[s] + ad);
        g_e[i] = e;
        m = fmaxf(m, e);
    }
#pragma unroll
    for (int o = 16; o > 0; o >>= 1) m = fmaxf(m, __shfl_xor_sync(0xffffffffu, m, o));

    float ssum = 0.f;
    float acc[FH];
#pragma unroll
    for (int j = 0; j < FH; j++) acc[j] = 0.f;

    if (lane == 0) {  // self-loop contribution
        float t = __expf(self_e - m);
        ssum = t;
        float4 h0 = g_h4[warp * 2], h1 = g_h4[warp * 2 + 1];
        acc[0] = t * h0.x; acc[1] = t * h0.y; acc[2] = t * h0.z; acc[3] = t * h0.w;
        acc[4] = t * h1.x; acc[5] = t * h1.y; acc[6] = t * h1.z; acc[7] = t * h1.w;
    }
    for (int i = beg + lane; i < end; i += 32) {
        int s = g_ssrc[i];
        float ex = __expf(g_e[i] - m);
        ssum += ex;
        float4 h0 = g_h4[s * 2], h1 = g_h4[s * 2 + 1];
        acc[0] = fmaf(ex, h0.x, acc[0]); acc[1] = fmaf(ex, h0.y, acc[1]);
        acc[2] = fmaf(ex, h0.z, acc[2]); acc[3] = fmaf(ex, h0.w, acc[3]);
        acc[4] = fmaf(ex, h1.x, acc[4]); acc[5] = fmaf(ex, h1.y, acc[5]);
        acc[6] = fmaf(ex, h1.z, acc[6]); acc[7] = fmaf(ex, h1.w, acc[7]);
    }
#pragma unroll
    for (int o = 16; o > 0; o >>= 1) {
        ssum += __shfl_xor_sync(0xffffffffu, ssum, o);
#pragma unroll
        for (int j = 0; j < FH; j++) acc[j] += __shfl_xor_sync(0xffffffffu, acc[j], o);
    }

    if (lane == 0) {
        float inv = 1.f / ssum;
        if (PHASE == 0) {
            float4 r0, r1;
            r0.x = acc[0] * inv + bv[0]; r0.y = acc[1] * inv + bv[1];
            r0.z = acc[2] * inv + bv[2]; r0.w = acc[3] * inv + bv[3];
            r1.x = acc[4] * inv + bv[4]; r1.y = acc[5] * inv + bv[5];
            r1.z = acc[6] * inv + bv[6]; r1.w = acc[7] * inv + bv[7];
            g_x14[warp * 2] = r0; g_x14[warp * 2 + 1] = r1;
        } else {
            float r = bl[0];
#pragma unroll
            for (int j = 0; j < FH; j++) r = fmaf(acc[j] * inv + bv[j], Wl[j], r);
            out[warp] = r >= 0.f ? r : 0.01f * r;
        }
    }
}

// ---------------- layer 2 transform ----------------
__global__ void k_h2(const float* __restrict__ W2,
                     const float* __restrict__ att_s, const float* __restrict__ att_d) {
    int n = blockIdx.x * blockDim.x + threadIdx.x;
    if (n >= NN) return;
    float xi[FH];
    const float4 a = g_x14[n * 2];
    const float4 b = g_x14[n * 2 + 1];
    xi[0] = a.x; xi[1] = a.y; xi[2] = a.z; xi[3] = a.w;
    xi[4] = b.x; xi[5] = b.y; xi[6] = b.z; xi[7] = b.w;
    float acc[FH];
#pragma unroll
    for (int j = 0; j < FH; j++) acc[j] = 0.f;
#pragma unroll
    for (int k = 0; k < FH; k++) {
        float xv = xi[k];
#pragma unroll
        for (int j = 0; j < FH; j++) acc[j] = fmaf(xv, __ldg(&W2[k * FH + j]), acc[j]);
    }
    float as = 0.f, ad = 0.f;
    float* gh = (float*)&g_h4[n * 2];
#pragma unroll
    for (int j = 0; j < FH; j++) {
        gh[j] = acc[j];
        as += acc[j] * __ldg(&att_s[j]);
        ad += acc[j] * __ldg(&att_d[j]);
    }
    g_as[n] = as;
    g_ad[n] = ad;
}

extern "C" void kernel_launch(void* const* d_in, const int* in_sizes, int n_in,
                              void* d_out, int out_size) {
    const float* x  = (const float*)d_in[0];
    const int*   ei = (const int*)d_in[1];      // int64 narrowed to int32 by harness
    const float* W1   = (const float*)d_in[4];
    const float* as1  = (const float*)d_in[5];
    const float* ad1  = (const float*)d_in[6];
    const float* b1   = (const float*)d_in[7];
    const float* W2   = (const float*)d_in[8];
    const float* as2  = (const float*)d_in[9];
    const float* ad2  = (const float*)d_in[10];
    const float* b2   = (const float*)d_in[11];
    const float* Wlin = (const float*)d_in[12];
    const float* blin = (const float*)d_in[13];
    float* out = (float*)d_out;

    const int E = in_sizes[1] / 2;

    const int TB = 256;
    const int gridN  = (NN + TB - 1) / TB;
    const int gridNW = (NN * 32 + TB - 1) / TB;   // warp-per-node kernels
    const int gridE  = (E + TB - 1) / TB;

    // layer-1 transform + CSR build (CSR shared by both layers)
    k_h1    <<<gridNW, TB>>>(x, W1, as1, ad1);
    k_count <<<gridE,  TB>>>(ei, E);
    k_scan1 <<<NBLK, SCANB>>>();
    k_scan2 <<<1, 32>>>();
    k_scan3 <<<gridN,  TB>>>(E);
    k_scatter<<<gridE, TB>>>(ei, E);

    // layer 1 aggregate
    k_gather<0><<<gridNW, TB>>>(b1, nullptr, nullptr, nullptr);

    // layer 2
    k_h2    <<<gridN,  TB>>>(W2, as2, ad2);
    k_gather<1><<<gridNW, TB>>>(b2, Wlin, blin, out);
}

// round 5
// speedup vs baseline: 1.7463x; 1.0374x over previous
#include <cuda_runtime.h>

#define NN     100000
#define FH     8
#define EMAX   3200000
#define FIN    256
#define SCANB  512
#define NBLK   ((NN + SCANB - 1) / SCANB)   // 196

// -------- device scratch --------
__device__ int    g_ssrc[EMAX];     // src sorted by dst (CSR adjacency)
__device__ int    g_deg [NN];
__device__ int    g_part[NN];
__device__ int    g_bsum[NBLK];
__device__ int    g_bsumx[NBLK];
__device__ int    g_off [NN + 1];   // CSR row offsets
__device__ int    g_cur [NN];       // scatter cursors
__device__ float4 g_h4  [NN * 2];   // layer-1 transformed features [NN,8]
__device__ float4 g_h4b [NN * 2];   // layer-2 transformed features [NN,8]

__device__ __forceinline__ float leaky02(float v) { return v >= 0.f ? v : 0.2f * v; }

// ---- zero degree counters --------------------------------------------------
__global__ void k_zero() {
    int n = blockIdx.x * blockDim.x + threadIdx.x;
    if (n < NN) g_deg[n] = 0;
}

// ---- layer 1 transform (warp/node) + fused degree count --------------------
__global__ void k_h1(const float* __restrict__ x, const float* __restrict__ W,
                     const int* __restrict__ ei, int E) {
    __shared__ float Ws[FIN * FH];
    for (int i = threadIdx.x; i < FIN * FH; i += blockDim.x) Ws[i] = W[i];
    __syncthreads();

    int gtid = blockIdx.x * blockDim.x + threadIdx.x;
    if (gtid < E) atomicAdd(&g_deg[ei[E + gtid]], 1);   // fused degree count

    int warp = gtid >> 5;
    int lane = threadIdx.x & 31;
    if (warp >= NN) return;

    const float* xr = x + (size_t)warp * FIN;
    float acc[FH];
#pragma unroll
    for (int j = 0; j < FH; j++) acc[j] = 0.f;
#pragma unroll
    for (int i = 0; i < FIN / 32; i++) {
        int k = i * 32 + lane;
        float xv = xr[k];
#pragma unroll
        for (int j = 0; j < FH; j++) acc[j] = fmaf(xv, Ws[k * FH + j], acc[j]);
    }
#pragma unroll
    for (int j = 0; j < FH; j++) {
#pragma unroll
        for (int o = 16; o > 0; o >>= 1) acc[j] += __shfl_xor_sync(0xffffffffu, acc[j], o);
    }
    float* gh = (float*)&g_h4[warp * 2];
    if (lane < FH) gh[lane] = acc[lane];
}

// ---- CSR scans -------------------------------------------------------------
__global__ void k_scan1() {
    __shared__ int sm[SCANB];
    int idx = blockIdx.x * SCANB + threadIdx.x;
    int v = (idx < NN) ? g_deg[idx] : 0;
    sm[threadIdx.x] = v;
    __syncthreads();
#pragma unroll
    for (int o = 1; o < SCANB; o <<= 1) {
        int t = (threadIdx.x >= o) ? sm[threadIdx.x - o] : 0;
        __syncthreads();
        sm[threadIdx.x] += t;
        __syncthreads();
    }
    if (idx < NN) g_part[idx] = sm[threadIdx.x] - v;   // exclusive
    if (threadIdx.x == SCANB - 1) g_bsum[blockIdx.x] = sm[SCANB - 1];
}

__global__ void k_scan2() {   // parallel scan of 196 block sums, 1 block
    __shared__ int sm[256];
    int v = (threadIdx.x < NBLK) ? g_bsum[threadIdx.x] : 0;
    sm[threadIdx.x] = v;
    __syncthreads();
#pragma unroll
    for (int o = 1; o < 256; o <<= 1) {
        int t = (threadIdx.x >= o) ? sm[threadIdx.x - o] : 0;
        __syncthreads();
        sm[threadIdx.x] += t;
        __syncthreads();
    }
    if (threadIdx.x < NBLK) g_bsumx[threadIdx.x] = sm[threadIdx.x] - v;  // exclusive
}

__global__ void k_scan3(int E) {
    int idx = blockIdx.x * blockDim.x + threadIdx.x;
    if (idx >= NN) return;
    int o = g_part[idx] + g_bsumx[idx >> 9];
    g_off[idx] = o;
    g_cur[idx] = o;
    if (idx == 0) g_off[NN] = E;
}

__global__ void k_scatter(const int* __restrict__ ei, int E) {
    int i = blockIdx.x * blockDim.x + threadIdx.x;
    if (i >= E) return;
    int s = ei[i];
    int d = ei[E + i];
    int pos = atomicAdd(&g_cur[d], 1);
    g_ssrc[pos] = s;
}

// ---- fused gather: single-pass online softmax + aggregate, warp per node ---
// PHASE 0: reads g_h4;  epilogue x1 = num/den + b, then h2 = x1 @ W2 -> g_h4b.
// PHASE 1: reads g_h4b; epilogue = linear head + LeakyReLU(0.01) -> out.
template <int PHASE>
__global__ void k_gather(const float* __restrict__ att_s, const float* __restrict__ att_d,
                         const float* __restrict__ bv,   const float* __restrict__ W2,
                         const float* __restrict__ Wl,   const float* __restrict__ bl,
                         float* __restrict__ out) {
    const float4* __restrict__ hbuf = (PHASE == 0) ? g_h4 : g_h4b;

    int warp = (blockIdx.x * blockDim.x + threadIdx.x) >> 5;
    int lane = threadIdx.x & 31;
    if (warp >= NN) return;

    // broadcast att_src into registers
    float A[FH];
#pragma unroll
    for (int j = 0; j < FH; j++) A[j] = __ldg(&att_s[j]);

    // this node's own h -> ad (dst logit part) and self-loop logit
    float4 hs0 = hbuf[warp * 2], hs1 = hbuf[warp * 2 + 1];
    float ad = hs0.x * __ldg(&att_d[0]) + hs0.y * __ldg(&att_d[1])
             + hs0.z * __ldg(&att_d[2]) + hs0.w * __ldg(&att_d[3])
             + hs1.x * __ldg(&att_d[4]) + hs1.y * __ldg(&att_d[5])
             + hs1.z * __ldg(&att_d[6]) + hs1.w * __ldg(&att_d[7]);
    float as_self = hs0.x * A[0] + hs0.y * A[1] + hs0.z * A[2] + hs0.w * A[3]
                  + hs1.x * A[4] + hs1.y * A[5] + hs1.z * A[6] + hs1.w * A[7];
    float self_e = leaky02(as_self + ad);

    // per-lane online softmax state; lane 0 seeded with the self-loop
    float m = -3.0e38f, s = 0.f;
    float acc[FH];
#pragma unroll
    for (int j = 0; j < FH; j++) acc[j] = 0.f;
    if (lane == 0) {
        m = self_e; s = 1.f;
        acc[0] = hs0.x; acc[1] = hs0.y; acc[2] = hs0.z; acc[3] = hs0.w;
        acc[4] = hs1.x; acc[5] = hs1.y; acc[6] = hs1.z; acc[7] = hs1.w;
    }

    int beg = g_off[warp], end = g_off[warp + 1];
    for (int i = beg + lane; i < end; i += 32) {
        int sidx = g_ssrc[i];
        float4 h0 = hbuf[sidx * 2], h1 = hbuf[sidx * 2 + 1];
        float as = h0.x * A[0] + h0.y * A[1] + h0.z * A[2] + h0.w * A[3]
                 + h1.x * A[4] + h1.y * A[5] + h1.z * A[6] + h1.w * A[7];
        float e  = leaky02(as + ad);
        float mn = fmaxf(m, e);
        float sc = __expf(m - mn);
        float w  = __expf(e - mn);
        s = s * sc + w;
        acc[0] = fmaf(acc[0], sc, w * h0.x); acc[1] = fmaf(acc[1], sc, w * h0.y);
        acc[2] = fmaf(acc[2], sc, w * h0.z); acc[3] = fmaf(acc[3], sc, w * h0.w);
        acc[4] = fmaf(acc[4], sc, w * h1.x); acc[5] = fmaf(acc[5], sc, w * h1.y);
        acc[6] = fmaf(acc[6], sc, w * h1.z); acc[7] = fmaf(acc[7], sc, w * h1.w);
        m = mn;
    }

    // merge lanes: global max, rescale, sum
    float M = m;
#pragma unroll
    for (int o = 16; o > 0; o >>= 1) M = fmaxf(M, __shfl_xor_sync(0xffffffffu, M, o));
    float c = __expf(m - M);
    s *= c;
#pragma unroll
    for (int j = 0; j < FH; j++) acc[j] *= c;
#pragma unroll
    for (int o = 16; o > 0; o >>= 1) {
        s += __shfl_xor_sync(0xffffffffu, s, o);
#pragma unroll
        for (int j = 0; j < FH; j++) acc[j] += __shfl_xor_sync(0xffffffffu, acc[j], o);
    }

    if (lane == 0) {
        float inv = 1.f / s;
        float xo[FH];
#pragma unroll
        for (int j = 0; j < FH; j++) xo[j] = acc[j] * inv + __ldg(&bv[j]);
        if (PHASE == 0) {
            // fused layer-2 transform: h2 = x1 @ W2  (8x8)
            float h2[FH];
#pragma unroll
            for (int k = 0; k < FH; k++) h2[k] = 0.f;
#pragma unroll
            for (int j = 0; j < FH; j++) {
                float xv = xo[j];
#pragma unroll
                for (int k = 0; k < FH; k++) h2[k] = fmaf(xv, __ldg(&W2[j * FH + k]), h2[k]);
            }
            float4 r0, r1;
            r0.x = h2[0]; r0.y = h2[1]; r0.z = h2[2]; r0.w = h2[3];
            r1.x = h2[4]; r1.y = h2[5]; r1.z = h2[6]; r1.w = h2[7];
            g_h4b[warp * 2]     = r0;
            g_h4b[warp * 2 + 1] = r1;
        } else {
            float r = __ldg(&bl[0]);
#pragma unroll
            for (int j = 0; j < FH; j++) r = fmaf(xo[j], __ldg(&Wl[j]), r);
            out[warp] = r >= 0.f ? r : 0.01f * r;
        }
    }
}

extern "C" void kernel_launch(void* const* d_in, const int* in_sizes, int n_in,
                              void* d_out, int out_size) {
    const float* x  = (const float*)d_in[0];
    const int*   ei = (const int*)d_in[1];      // int64 narrowed to int32 by harness
    const float* W1   = (const float*)d_in[4];
    const float* as1  = (const float*)d_in[5];
    const float* ad1  = (const float*)d_in[6];
    const float* b1   = (const float*)d_in[7];
    const float* W2   = (const float*)d_in[8];
    const float* as2  = (const float*)d_in[9];
    const float* ad2  = (const float*)d_in[10];
    const float* b2   = (const float*)d_in[11];
    const float* Wlin = (const float*)d_in[12];
    const float* blin = (const float*)d_in[13];
    float* out = (float*)d_out;

    const int E = in_sizes[1] / 2;

    const int TB = 256;
    const int gridN  = (NN + TB - 1) / TB;
    long long nwThreads = (long long)NN * 32;
    long long h1Threads = nwThreads > E ? nwThreads : E;   // cover both warps & edges
    const int gridH1 = (int)((h1Threads + TB - 1) / TB);
    const int gridNW = (int)((nwThreads + TB - 1) / TB);
    const int gridE  = (E + TB - 1) / TB;

    k_zero   <<<gridN,  TB>>>();
    k_h1     <<<gridH1, TB>>>(x, W1, ei, E);
    k_scan1  <<<NBLK, SCANB>>>();
    k_scan2  <<<1, 256>>>();
    k_scan3  <<<gridN,  TB>>>(E);
    k_scatter<<<gridE,  TB>>>(ei, E);

    k_gather<0><<<gridNW, TB>>>(as1, ad1, b1, W2, nullptr, nullptr, nullptr);
    k_gather<1><<<gridNW, TB>>>(as2, ad2, b2, nullptr, Wlin, blin, out);
}